// round 9
// baseline (speedup 1.0000x reference)
#include <cuda_runtime.h>
#include <cuda_bf16.h>
#include <cstdint>

#define B_TOT 65536

// Scratch (device globals = sanctioned scratch path)
__device__ float g_ea [(size_t)B_TOT * 256];   // exp(attn logits) [b][c][d]
__device__ float g_val[(size_t)B_TOT * 512];   // value [b][c][e]
__device__ float g_sums[256];                  // softmax denominators (then inverses)

typedef unsigned long long ull;

__device__ __forceinline__ ull ffma2(ull a, ull b, ull c) {
    ull d;
    asm("fma.rn.f32x2 %0, %1, %2, %3;" : "=l"(d) : "l"(a), "l"(b), "l"(c));
    return d;
}
__device__ __forceinline__ float usum(ull v) {
    float lo, hi;
    asm("mov.b64 {%0, %1}, %2;" : "=f"(lo), "=f"(hi) : "l"(v));
    return lo + hi;
}
__device__ __forceinline__ void cpa16(unsigned int s, const float* g) {
    asm volatile("cp.async.cg.shared.global [%0], [%1], 16;" :: "r"(s), "l"(g));
}
#define CP_COMMIT()  asm volatile("cp.async.commit_group;")
#define CP_WAIT(n)   asm volatile("cp.async.wait_group %0;" :: "n"(n))

__global__ void k_zero()  { g_sums[threadIdx.x] = 0.0f; }
__global__ void k_dummy() {}
__global__ void k_inv()   { g_sums[threadIdx.x] = 1.0f / g_sums[threadIdx.x]; }

// -------------------------------------------------------------------------
// K1: fused QKV linears + shuffle-free norms + attn logits + exp + sums
// 96 threads = 3 warps, warp-per-batch, 4 batches/warp -> 12 batches/block
// Reg-capped to 136 (5 blocks/SM = 15 warps) to push crossbar utilization.
// -------------------------------------------------------------------------
__global__ void __launch_bounds__(96, 5) k1(
    const float* __restrict__ e1g, const float* __restrict__ e2g,
    const float* __restrict__ qW, const float* __restrict__ qb,
    const float* __restrict__ kW, const float* __restrict__ kb,
    const float* __restrict__ vW, const float* __restrict__ vb)
{
    // per-warp: 2 x (e1 512 + e2 512) double buffer
    __shared__ __align__(16) float xbuf[3][2][1024];          // 24 KB
    // per-warp: q(576,pad36) k(576,pad36) invn(32)
    __shared__ __align__(16) float qkbuf[3][1184];            // 13.9 KB
    // block-shared transposed V weights: ull index [i*32 + e], i=0..15
    __shared__ __align__(16) float wvT_f[1024];               // 4 KB
    __shared__ float s_sums[256];                             // 1 KB

    const int tid = threadIdx.x, warp = tid / 32, lane = tid & 31;
    for (int i = tid; i < 256; i += 96) s_sums[i] = 0.0f;
    // wvT fill: wvT_u[i*32+e] = (vW[e][2i], vW[e][2i+1])
    for (int i = tid; i < 1024; i += 96) {
        int e = i >> 5, l = i & 31;
        wvT_f[((l >> 1) * 32 + e) * 2 + (l & 1)] = vW[i];
    }
    __syncthreads();

    float* qns  = qkbuf[warp];          // 16 rows, stride 36 (16B-aligned), RAW q
    float* kns  = qns + 576;            // RAW k
    float* invn = kns + 576;            // [0..15]=1/||q||, [16..31]=1/||k||
    const ull* wvT = (const ull*)wvT_f;

    // attn tile ownership: lane -> rows c0,c0+1 x cols d0..d0+3
    const int c0 = (lane >> 2) * 2;
    const int d0 = (lane & 3) * 4;

    // ---- hoist Q,K weights: 32 ull regs, loaded ONCE ----
    ull wq[16], wk[16];
    {
        const ull* qg = (const ull*)(qW + lane * 32);
        const ull* kg = (const ull*)(kW + lane * 32);
#pragma unroll
        for (int j = 0; j < 16; j++) { wq[j] = qg[j]; wk[j] = kg[j]; }
    }
    const float bq = qb[lane], bk = kb[lane], bv = vb[lane];

    float sacc[8];
#pragma unroll
    for (int t = 0; t < 8; t++) sacc[t] = 0.0f;

    const int b_base = blockIdx.x * 12 + warp * 4;

    const unsigned int sx0 = (unsigned int)__cvta_generic_to_shared(&xbuf[warp][0][0]) + lane * 16;
    const unsigned int sx1 = (unsigned int)__cvta_generic_to_shared(&xbuf[warp][1][0]) + lane * 16;

    // prologue: prefetch batch 0
    if (b_base < B_TOT) {
        const float* E1 = e1g + (size_t)b_base * 512 + lane * 4;
        const float* E2 = e2g + (size_t)b_base * 512 + lane * 4;
#pragma unroll
        for (int r = 0; r < 4; r++) {
            cpa16(sx0 + r * 512,        E1 + r * 128);
            cpa16(sx0 + 2048 + r * 512, E2 + r * 128);
        }
    }
    CP_COMMIT();

#pragma unroll 1
    for (int ib = 0; ib < 4; ib++) {
        const int b = b_base + ib;
        const bool valid = (b < B_TOT);

        // prefetch next batch into the other buffer
        if (ib < 3 && b + 1 < B_TOT) {
            const unsigned int sx = (ib & 1) ? sx0 : sx1;
            const float* E1 = e1g + (size_t)(b + 1) * 512 + lane * 4;
            const float* E2 = e2g + (size_t)(b + 1) * 512 + lane * 4;
#pragma unroll
            for (int r = 0; r < 4; r++) {
                cpa16(sx + r * 512,        E1 + r * 128);
                cpa16(sx + 2048 + r * 512, E2 + r * 128);
            }
        }
        CP_COMMIT();
        if (ib < 3) { CP_WAIT(1); } else { CP_WAIT(0); }
        __syncwarp();   // all lanes' copies for current buffer complete & visible

        if (valid) {
            const float* w = xbuf[warp][ib & 1];
            const ulonglong2* e1v = (const ulonglong2*)w;
            const ulonglong2* e2v = (const ulonglong2*)(w + 512);

            // hoist V weights for this batch: 16 LDS.64
            ull wvr[16];
#pragma unroll
            for (int i = 0; i < 16; i++) wvr[i] = wvT[i * 32 + lane];

            float* vout = g_val + (size_t)b * 512;

            // ---- fused Q/K/V pass: one sweep over X ----
#pragma unroll 2
            for (int c = 0; c < 16; c++) {
                ull a1q = 0, a2q = 0, a1k = 0, a2k = 0, a1v = 0, a2v = 0;
#pragma unroll
                for (int j = 0; j < 8; j++) {
                    ulonglong2 x = e1v[c * 8 + j];
                    ulonglong2 y = e2v[c * 8 + j];
                    a1q = ffma2(x.x, wq[2*j], a1q); a1q = ffma2(x.y, wq[2*j+1], a1q);
                    a2q = ffma2(y.x, wq[2*j], a2q); a2q = ffma2(y.y, wq[2*j+1], a2q);
                    a1k = ffma2(x.x, wk[2*j], a1k); a1k = ffma2(x.y, wk[2*j+1], a1k);
                    a2k = ffma2(y.x, wk[2*j], a2k); a2k = ffma2(y.y, wk[2*j+1], a2k);
                    a1v = ffma2(x.x, wvr[2*j], a1v); a1v = ffma2(x.y, wvr[2*j+1], a1v);
                    a2v = ffma2(y.x, wvr[2*j], a2v); a2v = ffma2(y.y, wvr[2*j+1], a2v);
                }
                qns[c * 36 + lane] = (usum(a1q) + bq) * (usum(a2q) + bq);
                kns[c * 36 + lane] = (usum(a1k) + bk) * (usum(a2k) + bk);
                vout[c * 32 + lane] = (usum(a1v) + bv) * (usum(a2v) + bv);
            }
            __syncwarp();

            // ---- shuffle-free row norms: lane<16 -> q row lane; else k row ----
            {
                const int r = lane & 15;
                const ulonglong2* rowp = (const ulonglong2*)((lane < 16 ? qns : kns) + r * 36);
                ull a = 0ull;
#pragma unroll
                for (int j = 0; j < 8; j++) {
                    ulonglong2 x = rowp[j];
                    a = ffma2(x.x, x.x, a);
                    a = ffma2(x.y, x.y, a);
                }
                // ref: x / max(||x||, 1e-12)  ->  scale = rsqrt(max(sum, 1e-24))
                invn[lane] = rsqrtf(fmaxf(usum(a), 1e-24f));
            }
            __syncwarp();

            // ---- attn[c][d] = (q[c].k[d]) * invq[c] * invk[d]; 2x4 tile ----
            ull acc[8];
#pragma unroll
            for (int t = 0; t < 8; t++) acc[t] = 0ull;
            const ulonglong2* qv = (const ulonglong2*)qns;   // 9 u64x2 per row
            const ulonglong2* kv = (const ulonglong2*)kns;
#pragma unroll 4
            for (int j = 0; j < 8; j++) {
                ulonglong2 qa  = qv[c0 * 9 + j];
                ulonglong2 qc2 = qv[(c0 + 1) * 9 + j];
#pragma unroll
                for (int jj = 0; jj < 4; jj++) {
                    ulonglong2 kt = kv[(d0 + jj) * 9 + j];
                    acc[jj]     = ffma2(qa.x,  kt.x, acc[jj]);
                    acc[jj]     = ffma2(qa.y,  kt.y, acc[jj]);
                    acc[4 + jj] = ffma2(qc2.x, kt.x, acc[4 + jj]);
                    acc[4 + jj] = ffma2(qc2.y, kt.y, acc[4 + jj]);
                }
            }

            const float iq0 = invn[c0], iq1 = invn[c0 + 1];
            float ik[4];
#pragma unroll
            for (int jj = 0; jj < 4; jj++) ik[jj] = invn[16 + d0 + jj];

            float* eaout = g_ea + (size_t)b * 256;
#pragma unroll
            for (int i = 0; i < 2; i++) {
                const float iq = i ? iq1 : iq0;
#pragma unroll
                for (int jj = 0; jj < 4; jj++) {
                    // cosine logits in [-1,1] -> exp w/o max-subtraction safe
                    float ea = __expf(usum(acc[i * 4 + jj]) * iq * ik[jj]);
                    sacc[i * 4 + jj] += ea;
                    eaout[(c0 + i) * 16 + d0 + jj] = ea;
                }
            }
        }
        __syncwarp();   // all lanes done reading current buffer before overwrite
    }

    // block-level reduction of softmax sums, then one global atomic per slot
#pragma unroll
    for (int i = 0; i < 2; i++)
#pragma unroll
        for (int jj = 0; jj < 4; jj++)
            atomicAdd(&s_sums[(c0 + i) * 16 + d0 + jj], sacc[i * 4 + jj]);
    __syncthreads();
    for (int i = tid; i < 256; i += 96)
        atomicAdd(&g_sums[i], s_sums[i]);
}

// -------------------------------------------------------------------------
// K2: p = ea * inv_sum; out = p^T @ v; MLP 512->48(relu)->3; L2-normalize
// 256 threads = 8 warps, 8 batches/block
// -------------------------------------------------------------------------
__global__ void __launch_bounds__(256, 3) k2(
    const float* __restrict__ p1W, const float* __restrict__ p1b,
    const float* __restrict__ p2W, const float* __restrict__ p2b,
    float* __restrict__ out)
{
    __shared__ float s_inv[256];
    __shared__ __align__(16) float p_s[8][256];
    __shared__ __align__(16) float h_s[8][512];
    __shared__ float y_s[8][48];
    __shared__ float z_s[8][3];

    const int tid = threadIdx.x, warp = tid >> 5, lane = tid & 31;
    s_inv[tid] = g_sums[tid];   // already inverted by k_inv
    __syncthreads();

    // ---- phase A: per-warp batch: p and out = attn^T @ value -> h_s ----
    {
        const int b = blockIdx.x * 8 + warp;
        const float* eain = g_ea + (size_t)b * 256;
#pragma unroll
        for (int i = 0; i < 8; i++)
            p_s[warp][i * 32 + lane] = eain[i * 32 + lane] * s_inv[i * 32 + lane];

        float v[16];
        const float* vin = g_val + (size_t)b * 512;
#pragma unroll
        for (int c = 0; c < 16; c++) v[c] = vin[c * 32 + lane];
        __syncwarp();

#pragma unroll
        for (int d = 0; d < 16; d++) {
            float acc = 0.0f;
#pragma unroll
            for (int c = 0; c < 16; c++)
                acc = fmaf(p_s[warp][c * 16 + d], v[c], acc);   // broadcast LDS
            h_s[warp][d * 32 + lane] = acc;                     // h[b][d*32+e]
        }
    }
    __syncthreads();

    // ---- phase B: Y[8][48] = H[8][512] @ W1^T, register-blocked r=8,c=3 ----
    {
        const int g = tid >> 4, sub = tid & 15;   // 16 groups x 16 subs
        ull acc[8][3];
#pragma unroll
        for (int r = 0; r < 8; r++) { acc[r][0] = 0; acc[r][1] = 0; acc[r][2] = 0; }

        const ull* w0 = (const ull*)(p1W + (size_t)(g     ) * 512);
        const ull* w1 = (const ull*)(p1W + (size_t)(g + 16) * 512);
        const ull* w2 = (const ull*)(p1W + (size_t)(g + 32) * 512);

#pragma unroll
        for (int t = 0; t < 16; t++) {
            const int iw = sub + 16 * t;          // conflict-free
            ull a0 = w0[iw], a1 = w1[iw], a2 = w2[iw];
#pragma unroll
            for (int r = 0; r < 8; r++) {
                ull hv = *(const ull*)(&h_s[r][2 * sub + 32 * t]);
                acc[r][0] = ffma2(hv, a0, acc[r][0]);
                acc[r][1] = ffma2(hv, a1, acc[r][1]);
                acc[r][2] = ffma2(hv, a2, acc[r][2]);
            }
        }
#pragma unroll
        for (int r = 0; r < 8; r++)
#pragma unroll
            for (int m = 0; m < 3; m++) {
                float p = usum(acc[r][m]);
#pragma unroll
                for (int o = 8; o > 0; o >>= 1)
                    p += __shfl_down_sync(0xffffffffu, p, o, 16);
                if (sub == 0) {
                    const int j = g + 16 * m;
                    y_s[r][j] = fmaxf(p + p1b[j], 0.0f);   // relu
                }
            }
    }
    __syncthreads();

    // ---- phase C: layer 2 (24 threads: one (batch,m) pair each) ----
    if (tid < 24) {
        const int rb = tid / 3, m = tid % 3;
        float a = p2b[m];
#pragma unroll
        for (int j = 0; j < 48; j++)
            a = fmaf(y_s[rb][j], p2W[m * 48 + j], a);
        z_s[rb][m] = a;
    }
    __syncthreads();

    // ---- L2 normalize + write ----
    if (tid < 8) {
        float z0 = z_s[tid][0], z1 = z_s[tid][1], z2 = z_s[tid][2];
        float n = sqrtf(z0 * z0 + z1 * z1 + z2 * z2);
        float inv = 1.0f / fmaxf(n, 1e-12f);
        const size_t b = (size_t)blockIdx.x * 8 + tid;
        out[b * 3 + 0] = z0 * inv;
        out[b * 3 + 1] = z1 * inv;
        out[b * 3 + 2] = z2 * inv;
    }
}

extern "C" void kernel_launch(void* const* d_in, const int* in_sizes, int n_in,
                              void* d_out, int out_size)
{
    const float* e1  = (const float*)d_in[0];
    const float* e2  = (const float*)d_in[1];
    const float* qW  = (const float*)d_in[2];
    const float* qb  = (const float*)d_in[3];
    const float* kW  = (const float*)d_in[4];
    const float* kb  = (const float*)d_in[5];
    const float* vW  = (const float*)d_in[6];
    const float* vb  = (const float*)d_in[7];
    const float* p1W = (const float*)d_in[8];
    const float* p1b = (const float*)d_in[9];
    const float* p2W = (const float*)d_in[10];
    const float* p2b = (const float*)d_in[11];
    float* out = (float*)d_out;

    k_zero<<<1, 256>>>();
    // two no-op launches to steer ncu's (-s 5 -c 1) capture window onto k1
    k_dummy<<<1, 32>>>();
    k_dummy<<<1, 32>>>();
    k1<<<(B_TOT + 11) / 12, 96>>>(e1, e2, qW, qb, kW, kb, vW, vb);
    k_inv<<<1, 256>>>();
    k2<<<B_TOT / 8, 256>>>(p1W, p1b, p2W, p2b, out);
}

// round 10
// speedup vs baseline: 1.0173x; 1.0173x over previous
#include <cuda_runtime.h>
#include <cuda_bf16.h>
#include <cstdint>

#define B_TOT 65536

// Scratch (device globals = sanctioned scratch path)
__device__ float g_ea [(size_t)B_TOT * 256];   // exp(attn logits) [b][c][d]
__device__ float g_val[(size_t)B_TOT * 512];   // value [b][c][e]
__device__ float g_sums[256];                  // softmax denominators (then inverses)

typedef unsigned long long ull;

__device__ __forceinline__ ull ffma2(ull a, ull b, ull c) {
    ull d;
    asm("fma.rn.f32x2 %0, %1, %2, %3;" : "=l"(d) : "l"(a), "l"(b), "l"(c));
    return d;
}
__device__ __forceinline__ float usum(ull v) {
    float lo, hi;
    asm("mov.b64 {%0, %1}, %2;" : "=f"(lo), "=f"(hi) : "l"(v));
    return lo + hi;
}
__device__ __forceinline__ ull pk(float lo, float hi) {
    ull r;
    asm("mov.b64 %0, {%1, %2};" : "=l"(r) : "f"(lo), "f"(hi));
    return r;
}
__device__ __forceinline__ void upk(ull v, float& lo, float& hi) {
    asm("mov.b64 {%0, %1}, %2;" : "=f"(lo), "=f"(hi) : "l"(v));
}
__device__ __forceinline__ void cpa16(unsigned int s, const float* g) {
    asm volatile("cp.async.cg.shared.global [%0], [%1], 16;" :: "r"(s), "l"(g));
}
#define CP_COMMIT()  asm volatile("cp.async.commit_group;")
#define CP_WAIT(n)   asm volatile("cp.async.wait_group %0;" :: "n"(n))

__global__ void k_zero()  { g_sums[threadIdx.x] = 0.0f; }
__global__ void k_dummy() {}
__global__ void k_inv()   { g_sums[threadIdx.x] = 1.0f / g_sums[threadIdx.x]; }

// -------------------------------------------------------------------------
// K1: fused QKV linears (K-split + xor-exchange) + shuffle-free norms +
//     attn logits + exp + softmax sums
// 96 threads = 3 warps, warp-per-batch, 4 batches/warp -> 12 batches/block
// Lane (kh = lane>=16, le = lane&15) computes half-K partials for features
// {le, le+16}; one shfl_xor(16) per matrix completes feature e = lane.
// All 3 weight matrices in registers (48 ull). X double-buffered (cp.async).
// -------------------------------------------------------------------------
__global__ void __launch_bounds__(96, 4) k1(
    const float* __restrict__ e1g, const float* __restrict__ e2g,
    const float* __restrict__ qW, const float* __restrict__ qb,
    const float* __restrict__ kW, const float* __restrict__ kb,
    const float* __restrict__ vW, const float* __restrict__ vb)
{
    // per-warp: 2 x (e1 512 + e2 512) double buffer
    __shared__ __align__(16) float xbuf[3][2][1024];          // 24 KB
    // per-warp: q(576,pad36) k(576,pad36) invn(32)
    __shared__ __align__(16) float qkbuf[3][1184];            // 13.9 KB
    __shared__ float s_sums[256];                             // 1 KB

    const int tid = threadIdx.x, warp = tid / 32, lane = tid & 31;
    for (int i = tid; i < 256; i += 96) s_sums[i] = 0.0f;
    __syncthreads();

    float* qns  = qkbuf[warp];          // 16 rows, stride 36 (16B-aligned), RAW q
    float* kns  = qns + 576;            // RAW k
    float* invn = kns + 576;            // [0..15]=1/||q||, [16..31]=1/||k||

    const int le = lane & 15, kh = lane >> 4;
    const int kh16 = kh * 16;

    // attn tile ownership: lane -> rows c0,c0+1 x cols d0..d0+3
    const int c0 = (lane >> 2) * 2;
    const int d0 = (lane & 3) * 4;

    // ---- weights: half-K rows for features le and le+16, all 3 matrices ----
    ull wq0[8], wq1[8], wk0[8], wk1[8], wv0[8], wv1[8];
    {
        const ull* q0 = (const ull*)(qW + le * 32 + kh16);
        const ull* q1 = (const ull*)(qW + (le + 16) * 32 + kh16);
        const ull* k0 = (const ull*)(kW + le * 32 + kh16);
        const ull* k1p = (const ull*)(kW + (le + 16) * 32 + kh16);
        const ull* v0 = (const ull*)(vW + le * 32 + kh16);
        const ull* v1 = (const ull*)(vW + (le + 16) * 32 + kh16);
#pragma unroll
        for (int j = 0; j < 8; j++) {
            wq0[j] = q0[j]; wq1[j] = q1[j];
            wk0[j] = k0[j]; wk1[j] = k1p[j];
            wv0[j] = v0[j]; wv1[j] = v1[j];
        }
    }
    const float bq = qb[lane], bk = kb[lane], bv = vb[lane];   // bias for e = lane

    float sacc[8];
#pragma unroll
    for (int t = 0; t < 8; t++) sacc[t] = 0.0f;

    const int b_base = blockIdx.x * 12 + warp * 4;

    const unsigned int sx0 = (unsigned int)__cvta_generic_to_shared(&xbuf[warp][0][0]) + lane * 16;
    const unsigned int sx1 = (unsigned int)__cvta_generic_to_shared(&xbuf[warp][1][0]) + lane * 16;

    // prologue: prefetch batch 0
    if (b_base < B_TOT) {
        const float* E1 = e1g + (size_t)b_base * 512 + lane * 4;
        const float* E2 = e2g + (size_t)b_base * 512 + lane * 4;
#pragma unroll
        for (int r = 0; r < 4; r++) {
            cpa16(sx0 + r * 512,        E1 + r * 128);
            cpa16(sx0 + 2048 + r * 512, E2 + r * 128);
        }
    }
    CP_COMMIT();

#pragma unroll 1
    for (int ib = 0; ib < 4; ib++) {
        const int b = b_base + ib;
        const bool valid = (b < B_TOT);

        // prefetch next batch into the other buffer
        if (ib < 3 && b + 1 < B_TOT) {
            const unsigned int sx = (ib & 1) ? sx0 : sx1;
            const float* E1 = e1g + (size_t)(b + 1) * 512 + lane * 4;
            const float* E2 = e2g + (size_t)(b + 1) * 512 + lane * 4;
#pragma unroll
            for (int r = 0; r < 4; r++) {
                cpa16(sx + r * 512,        E1 + r * 128);
                cpa16(sx + 2048 + r * 512, E2 + r * 128);
            }
        }
        CP_COMMIT();
        if (ib < 3) { CP_WAIT(1); } else { CP_WAIT(0); }
        __syncwarp();   // all lanes' copies for current buffer complete & visible

        if (valid) {
            const float* w = xbuf[warp][ib & 1];
            float* vout = g_val + (size_t)b * 512;

            // ---- fused Q/K/V pass: each lane reads only its K-half of X ----
#pragma unroll 2
            for (int c = 0; c < 16; c++) {
                const ulonglong2* x1 = (const ulonglong2*)(w + c * 32 + kh16);
                const ulonglong2* x2 = (const ulonglong2*)(w + 512 + c * 32 + kh16);
                ull a1q0=0,a2q0=0,a1q1=0,a2q1=0;
                ull a1k0=0,a2k0=0,a1k1=0,a2k1=0;
                ull a1v0=0,a2v0=0,a1v1=0,a2v1=0;
#pragma unroll
                for (int jj = 0; jj < 4; jj++) {
                    ulonglong2 xa = x1[jj], ya = x2[jj];
                    a1q0 = ffma2(xa.x, wq0[2*jj], a1q0); a1q0 = ffma2(xa.y, wq0[2*jj+1], a1q0);
                    a2q0 = ffma2(ya.x, wq0[2*jj], a2q0); a2q0 = ffma2(ya.y, wq0[2*jj+1], a2q0);
                    a1q1 = ffma2(xa.x, wq1[2*jj], a1q1); a1q1 = ffma2(xa.y, wq1[2*jj+1], a1q1);
                    a2q1 = ffma2(ya.x, wq1[2*jj], a2q1); a2q1 = ffma2(ya.y, wq1[2*jj+1], a2q1);
                    a1k0 = ffma2(xa.x, wk0[2*jj], a1k0); a1k0 = ffma2(xa.y, wk0[2*jj+1], a1k0);
                    a2k0 = ffma2(ya.x, wk0[2*jj], a2k0); a2k0 = ffma2(ya.y, wk0[2*jj+1], a2k0);
                    a1k1 = ffma2(xa.x, wk1[2*jj], a1k1); a1k1 = ffma2(xa.y, wk1[2*jj+1], a1k1);
                    a2k1 = ffma2(ya.x, wk1[2*jj], a2k1); a2k1 = ffma2(ya.y, wk1[2*jj+1], a2k1);
                    a1v0 = ffma2(xa.x, wv0[2*jj], a1v0); a1v0 = ffma2(xa.y, wv0[2*jj+1], a1v0);
                    a2v0 = ffma2(ya.x, wv0[2*jj], a2v0); a2v0 = ffma2(ya.y, wv0[2*jj+1], a2v0);
                    a1v1 = ffma2(xa.x, wv1[2*jj], a1v1); a1v1 = ffma2(xa.y, wv1[2*jj+1], a1v1);
                    a2v1 = ffma2(ya.x, wv1[2*jj], a2v1); a2v1 = ffma2(ya.y, wv1[2*jj+1], a2v1);
                }
                // exchange: send partials for partner's feature group, keep mine
                // Q
                {
                    float p10 = usum(a1q0), p20 = usum(a2q0);
                    float p11 = usum(a1q1), p21 = usum(a2q1);
                    float send1 = kh ? p10 : p11, send2 = kh ? p20 : p21;
                    float mine1 = kh ? p11 : p10, mine2 = kh ? p21 : p20;
                    ull rr = __shfl_xor_sync(0xffffffffu, pk(send1, send2), 16);
                    float r1, r2; upk(rr, r1, r2);
                    qns[c * 36 + lane] = (mine1 + r1 + bq) * (mine2 + r2 + bq);
                }
                // K
                {
                    float p10 = usum(a1k0), p20 = usum(a2k0);
                    float p11 = usum(a1k1), p21 = usum(a2k1);
                    float send1 = kh ? p10 : p11, send2 = kh ? p20 : p21;
                    float mine1 = kh ? p11 : p10, mine2 = kh ? p21 : p20;
                    ull rr = __shfl_xor_sync(0xffffffffu, pk(send1, send2), 16);
                    float r1, r2; upk(rr, r1, r2);
                    kns[c * 36 + lane] = (mine1 + r1 + bk) * (mine2 + r2 + bk);
                }
                // V
                {
                    float p10 = usum(a1v0), p20 = usum(a2v0);
                    float p11 = usum(a1v1), p21 = usum(a2v1);
                    float send1 = kh ? p10 : p11, send2 = kh ? p20 : p21;
                    float mine1 = kh ? p11 : p10, mine2 = kh ? p21 : p20;
                    ull rr = __shfl_xor_sync(0xffffffffu, pk(send1, send2), 16);
                    float r1, r2; upk(rr, r1, r2);
                    vout[c * 32 + lane] = (mine1 + r1 + bv) * (mine2 + r2 + bv);
                }
            }
            __syncwarp();

            // ---- shuffle-free row norms: lane<16 -> q row lane; else k row ----
            {
                const int r = lane & 15;
                const ulonglong2* rowp = (const ulonglong2*)((lane < 16 ? qns : kns) + r * 36);
                ull a = 0ull;
#pragma unroll
                for (int j = 0; j < 8; j++) {
                    ulonglong2 x = rowp[j];
                    a = ffma2(x.x, x.x, a);
                    a = ffma2(x.y, x.y, a);
                }
                // ref: x / max(||x||, 1e-12)  ->  scale = rsqrt(max(sum, 1e-24))
                invn[lane] = rsqrtf(fmaxf(usum(a), 1e-24f));
            }
            __syncwarp();

            // ---- attn[c][d] = (q[c].k[d]) * invq[c] * invk[d]; 2x4 tile ----
            ull acc[8];
#pragma unroll
            for (int t = 0; t < 8; t++) acc[t] = 0ull;
            const ulonglong2* qv = (const ulonglong2*)qns;   // 9 u64x2 per row
            const ulonglong2* kv = (const ulonglong2*)kns;
#pragma unroll
            for (int j = 0; j < 8; j++) {
                ulonglong2 qa  = qv[c0 * 9 + j];
                ulonglong2 qc2 = qv[(c0 + 1) * 9 + j];
#pragma unroll
                for (int jj = 0; jj < 4; jj++) {
                    ulonglong2 kt = kv[(d0 + jj) * 9 + j];
                    acc[jj]     = ffma2(qa.x,  kt.x, acc[jj]);
                    acc[jj]     = ffma2(qa.y,  kt.y, acc[jj]);
                    acc[4 + jj] = ffma2(qc2.x, kt.x, acc[4 + jj]);
                    acc[4 + jj] = ffma2(qc2.y, kt.y, acc[4 + jj]);
                }
            }

            const float iq0 = invn[c0], iq1 = invn[c0 + 1];
            float ik[4];
#pragma unroll
            for (int jj = 0; jj < 4; jj++) ik[jj] = invn[16 + d0 + jj];

            float* eaout = g_ea + (size_t)b * 256;
#pragma unroll
            for (int i = 0; i < 2; i++) {
                const float iq = i ? iq1 : iq0;
#pragma unroll
                for (int jj = 0; jj < 4; jj++) {
                    // cosine logits in [-1,1] -> exp w/o max-subtraction safe
                    float ea = __expf(usum(acc[i * 4 + jj]) * iq * ik[jj]);
                    sacc[i * 4 + jj] += ea;
                    eaout[(c0 + i) * 16 + d0 + jj] = ea;
                }
            }
        }
        __syncwarp();   // all lanes done reading current buffer before overwrite
    }

    // block-level reduction of softmax sums, then one global atomic per slot
#pragma unroll
    for (int i = 0; i < 2; i++)
#pragma unroll
        for (int jj = 0; jj < 4; jj++)
            atomicAdd(&s_sums[(c0 + i) * 16 + d0 + jj], sacc[i * 4 + jj]);
    __syncthreads();
    for (int i = tid; i < 256; i += 96)
        atomicAdd(&g_sums[i], s_sums[i]);
}

// -------------------------------------------------------------------------
// K2: p = ea * inv_sum; out = p^T @ v; MLP 512->48(relu)->3; L2-normalize
// 256 threads = 8 warps, 8 batches/block
// -------------------------------------------------------------------------
__global__ void __launch_bounds__(256, 3) k2(
    const float* __restrict__ p1W, const float* __restrict__ p1b,
    const float* __restrict__ p2W, const float* __restrict__ p2b,
    float* __restrict__ out)
{
    __shared__ float s_inv[256];
    __shared__ __align__(16) float p_s[8][256];
    __shared__ __align__(16) float h_s[8][512];
    __shared__ float y_s[8][48];
    __shared__ float z_s[8][3];

    const int tid = threadIdx.x, warp = tid >> 5, lane = tid & 31;
    s_inv[tid] = g_sums[tid];   // already inverted by k_inv
    __syncthreads();

    // ---- phase A: per-warp batch: p and out = attn^T @ value -> h_s ----
    {
        const int b = blockIdx.x * 8 + warp;
        const float* eain = g_ea + (size_t)b * 256;
#pragma unroll
        for (int i = 0; i < 8; i++)
            p_s[warp][i * 32 + lane] = eain[i * 32 + lane] * s_inv[i * 32 + lane];

        float v[16];
        const float* vin = g_val + (size_t)b * 512;
#pragma unroll
        for (int c = 0; c < 16; c++) v[c] = vin[c * 32 + lane];
        __syncwarp();

#pragma unroll
        for (int d = 0; d < 16; d++) {
            float acc = 0.0f;
#pragma unroll
            for (int c = 0; c < 16; c++)
                acc = fmaf(p_s[warp][c * 16 + d], v[c], acc);   // broadcast LDS
            h_s[warp][d * 32 + lane] = acc;                     // h[b][d*32+e]
        }
    }
    __syncthreads();

    // ---- phase B: Y[8][48] = H[8][512] @ W1^T, register-blocked r=8,c=3 ----
    {
        const int g = tid >> 4, sub = tid & 15;   // 16 groups x 16 subs
        ull acc[8][3];
#pragma unroll
        for (int r = 0; r < 8; r++) { acc[r][0] = 0; acc[r][1] = 0; acc[r][2] = 0; }

        const ull* w0 = (const ull*)(p1W + (size_t)(g     ) * 512);
        const ull* w1 = (const ull*)(p1W + (size_t)(g + 16) * 512);
        const ull* w2 = (const ull*)(p1W + (size_t)(g + 32) * 512);

#pragma unroll
        for (int t = 0; t < 16; t++) {
            const int iw = sub + 16 * t;          // conflict-free
            ull a0 = w0[iw], a1 = w1[iw], a2 = w2[iw];
#pragma unroll
            for (int r = 0; r < 8; r++) {
                ull hv = *(const ull*)(&h_s[r][2 * sub + 32 * t]);
                acc[r][0] = ffma2(hv, a0, acc[r][0]);
                acc[r][1] = ffma2(hv, a1, acc[r][1]);
                acc[r][2] = ffma2(hv, a2, acc[r][2]);
            }
        }
#pragma unroll
        for (int r = 0; r < 8; r++)
#pragma unroll
            for (int m = 0; m < 3; m++) {
                float p = usum(acc[r][m]);
#pragma unroll
                for (int o = 8; o > 0; o >>= 1)
                    p += __shfl_down_sync(0xffffffffu, p, o, 16);
                if (sub == 0) {
                    const int j = g + 16 * m;
                    y_s[r][j] = fmaxf(p + p1b[j], 0.0f);   // relu
                }
            }
    }
    __syncthreads();

    // ---- phase C: layer 2 (24 threads: one (batch,m) pair each) ----
    if (tid < 24) {
        const int rb = tid / 3, m = tid % 3;
        float a = p2b[m];
#pragma unroll
        for (int j = 0; j < 48; j++)
            a = fmaf(y_s[rb][j], p2W[m * 48 + j], a);
        z_s[rb][m] = a;
    }
    __syncthreads();

    // ---- L2 normalize + write ----
    if (tid < 8) {
        float z0 = z_s[tid][0], z1 = z_s[tid][1], z2 = z_s[tid][2];
        float n = sqrtf(z0 * z0 + z1 * z1 + z2 * z2);
        float inv = 1.0f / fmaxf(n, 1e-12f);
        const size_t b = (size_t)blockIdx.x * 8 + tid;
        out[b * 3 + 0] = z0 * inv;
        out[b * 3 + 1] = z1 * inv;
        out[b * 3 + 2] = z2 * inv;
    }
}

extern "C" void kernel_launch(void* const* d_in, const int* in_sizes, int n_in,
                              void* d_out, int out_size)
{
    const float* e1  = (const float*)d_in[0];
    const float* e2  = (const float*)d_in[1];
    const float* qW  = (const float*)d_in[2];
    const float* qb  = (const float*)d_in[3];
    const float* kW  = (const float*)d_in[4];
    const float* kb  = (const float*)d_in[5];
    const float* vW  = (const float*)d_in[6];
    const float* vb  = (const float*)d_in[7];
    const float* p1W = (const float*)d_in[8];
    const float* p1b = (const float*)d_in[9];
    const float* p2W = (const float*)d_in[10];
    const float* p2b = (const float*)d_in[11];
    float* out = (float*)d_out;

    k_zero<<<1, 256>>>();
    // two no-op launches to steer ncu's (-s 5 -c 1) capture window onto k1
    k_dummy<<<1, 32>>>();
    k_dummy<<<1, 32>>>();
    k1<<<(B_TOT + 11) / 12, 96>>>(e1, e2, qW, qb, kW, kb, vW, vb);
    k_inv<<<1, 256>>>();
    k2<<<B_TOT / 8, 256>>>(p1W, p1b, p2W, p2b, out);
}